// round 6
// baseline (speedup 1.0000x reference)
#include <cuda_runtime.h>
#include <cuda_bf16.h>
#include <cstdint>
#include <math.h>

// Problem constants
#define BB 4
#define TT 16
#define SS 256
#define DD 1024
#define HH 16
#define HKV 4
#define HD 64
#define NSEQ (BB*TT)          // 64
#define NROWS (NSEQ*SS)       // 16384
#define N_IMG 240

// Scratch (device globals: allocation-free)
__device__ float g_Q[NROWS * DD];          // 64 MB
__device__ float g_K[NROWS * HKV * HD];    // 16 MB
__device__ float g_V[NROWS * HKV * HD];    // 16 MB
__device__ float g_AO[NROWS * DD];         // 64 MB

// ---------------------------------------------------------------------------
__device__ __forceinline__ float to_tf32(float x) {
    float y;
    asm("cvt.rna.tf32.f32 %0, %1;" : "=f"(y) : "f"(x));
    return y;
}

__device__ __forceinline__ void mma_tf32(float* d, const uint32_t* a, const uint32_t* b) {
    asm volatile(
        "mma.sync.aligned.m16n8k8.row.col.f32.tf32.tf32.f32 "
        "{%0,%1,%2,%3}, {%4,%5,%6,%7}, {%8,%9}, {%0,%1,%2,%3};"
        : "+f"(d[0]), "+f"(d[1]), "+f"(d[2]), "+f"(d[3])
        : "r"(a[0]), "r"(a[1]), "r"(a[2]), "r"(a[3]), "r"(b[0]), "r"(b[1]));
}

// ---------------------------------------------------------------------------
// TF32 mma.sync GEMM: C[M,N] = A[M,K] * W[K,N], all row-major.
// Tile 128x128, BK=32, 256 threads; warp tile 64x32 (4x4 of m16n8k8).
// Double-buffered smem, one sync per k-chunk, register-prefetched LDG.
// As[m][k] stride 36 (bank-conflict-free a-frags); Bs[k][n] stride 136.
// ---------------------------------------------------------------------------
#define A_STRIDE 36
#define B_STRIDE 136
#define A_SZ (128 * A_STRIDE)          // floats per buffer
#define B_SZ (32 * B_STRIDE)
#define GEMM_SMEM ((2 * (A_SZ + B_SZ)) * (int)sizeof(float))  // 71680 B

__global__ __launch_bounds__(256) void gemm_mma_tf32(
    const float* __restrict__ A, const float* __restrict__ W,
    float* __restrict__ C, int N, int K)
{
    extern __shared__ float sm[];
    float* As[2] = { sm, sm + A_SZ };
    float* Bs[2] = { sm + 2 * A_SZ, sm + 2 * A_SZ + B_SZ };

    const int tid  = threadIdx.x;
    const int wid  = tid >> 5;
    const int lane = tid & 31;
    const int grp  = lane >> 2;        // 0..7
    const int tig  = lane & 3;         // 0..3
    const int m_off = (wid & 1) * 64;  // warp m offset in tile
    const int n_off = (wid >> 1) * 32; // warp n offset in tile

    const int m0 = blockIdx.y * 128;
    const int n0 = blockIdx.x * 128;

    float acc[4][4][4];
    #pragma unroll
    for (int mt = 0; mt < 4; mt++)
        #pragma unroll
        for (int nt = 0; nt < 4; nt++)
            #pragma unroll
            for (int i = 0; i < 4; i++) acc[mt][nt][i] = 0.f;

    float4 ldA[4], ldB[4];

    // Prologue LDG (kt = 0)
    #pragma unroll
    for (int s = 0; s < 4; s++) {
        int idx = tid + s * 256;
        int am = idx >> 3, ak4 = idx & 7;
        ldA[s] = *(const float4*)(A + (size_t)(m0 + am) * K + ak4 * 4);
        int bk = idx >> 5, bn4 = idx & 31;
        ldB[s] = *(const float4*)(W + (size_t)bk * N + n0 + bn4 * 4);
    }

    const int KT = K >> 5;
    for (int kt = 0; kt < KT; kt++) {
        float* Ab = As[kt & 1];
        float* Bb = Bs[kt & 1];
        // STS with RNA tf32 rounding
        #pragma unroll
        for (int s = 0; s < 4; s++) {
            int idx = tid + s * 256;
            int am = idx >> 3, ak4 = idx & 7;
            float4 v = ldA[s];
            *(float4*)(Ab + am * A_STRIDE + ak4 * 4) = make_float4(
                to_tf32(v.x), to_tf32(v.y), to_tf32(v.z), to_tf32(v.w));
            int bk = idx >> 5, bn4 = idx & 31;
            float4 w = ldB[s];
            *(float4*)(Bb + bk * B_STRIDE + bn4 * 4) = make_float4(
                to_tf32(w.x), to_tf32(w.y), to_tf32(w.z), to_tf32(w.w));
        }
        __syncthreads();
        if (kt + 1 < KT) {
            const int kn = (kt + 1) * 32;
            #pragma unroll
            for (int s = 0; s < 4; s++) {
                int idx = tid + s * 256;
                int am = idx >> 3, ak4 = idx & 7;
                ldA[s] = *(const float4*)(A + (size_t)(m0 + am) * K + kn + ak4 * 4);
                int bk = idx >> 5, bn4 = idx & 31;
                ldB[s] = *(const float4*)(W + (size_t)(kn + bk) * N + n0 + bn4 * 4);
            }
        }
        // Compute 4 k-steps of 8
        #pragma unroll
        for (int ks = 0; ks < 4; ks++) {
            const int k = ks * 8;
            uint32_t af[4][4], bf[4][2];
            #pragma unroll
            for (int mt = 0; mt < 4; mt++) {
                const int row = m_off + mt * 16 + grp;
                af[mt][0] = __float_as_uint(Ab[row * A_STRIDE + k + tig]);
                af[mt][1] = __float_as_uint(Ab[(row + 8) * A_STRIDE + k + tig]);
                af[mt][2] = __float_as_uint(Ab[row * A_STRIDE + k + tig + 4]);
                af[mt][3] = __float_as_uint(Ab[(row + 8) * A_STRIDE + k + tig + 4]);
            }
            #pragma unroll
            for (int nt = 0; nt < 4; nt++) {
                const int col = n_off + nt * 8 + grp;
                bf[nt][0] = __float_as_uint(Bb[(k + tig) * B_STRIDE + col]);
                bf[nt][1] = __float_as_uint(Bb[(k + tig + 4) * B_STRIDE + col]);
            }
            #pragma unroll
            for (int mt = 0; mt < 4; mt++)
                #pragma unroll
                for (int nt = 0; nt < 4; nt++)
                    mma_tf32(acc[mt][nt], af[mt], bf[nt]);
        }
    }

    // Epilogue
    #pragma unroll
    for (int mt = 0; mt < 4; mt++) {
        const int row = m0 + m_off + mt * 16 + grp;
        #pragma unroll
        for (int nt = 0; nt < 4; nt++) {
            const int col = n0 + n_off + nt * 8 + 2 * tig;
            *(float2*)(C + (size_t)row * N + col) =
                make_float2(acc[mt][nt][0], acc[mt][nt][1]);
            *(float2*)(C + (size_t)(row + 8) * N + col) =
                make_float2(acc[mt][nt][2], acc[mt][nt][3]);
        }
    }
}

// ---------------------------------------------------------------------------
// RMSNorm + RoPE, in place on g_Q and g_K. One warp per 64-wide head row.
// ---------------------------------------------------------------------------
__global__ __launch_bounds__(256) void normrope_kernel(
    const float* __restrict__ rope_cos, const float* __restrict__ rope_sin,
    const float* __restrict__ q_scale, const float* __restrict__ k_scale)
{
    const int w    = blockIdx.x * 8 + (threadIdx.x >> 5);
    const int lane = threadIdx.x & 31;

    float* ptr;
    const float* sc;
    int s;
    const int NQ = NROWS * HH;
    if (w < NQ) {
        int ns = w >> 4;
        int h  = w & 15;
        ptr = g_Q + (size_t)ns * DD + h * HD;
        s   = ns & (SS - 1);
        sc  = q_scale;
    } else {
        int r  = w - NQ;
        int ns = r >> 2;
        int hk = r & 3;
        ptr = g_K + (size_t)ns * (HKV * HD) + hk * HD;
        s   = ns & (SS - 1);
        sc  = k_scale;
    }

    float a = ptr[lane];
    float b = ptr[lane + 32];
    float ssq = a * a + b * b;
    #pragma unroll
    for (int off = 16; off > 0; off >>= 1)
        ssq += __shfl_xor_sync(0xFFFFFFFFu, ssq, off);
    float r = rsqrtf(ssq * (1.0f / 64.0f) + 1e-6f);

    float an = a * r * sc[lane];
    float bn = b * r * sc[lane + 32];
    float c  = rope_cos[s * 32 + lane];
    float sn = rope_sin[s * 32 + lane];
    ptr[lane]      = an * c - bn * sn;
    ptr[lane + 32] = bn * c + an * sn;
}

// ---------------------------------------------------------------------------
// Attention: one CTA per (seq n, head h). K/V tile in smem (128 KB dynamic).
// ---------------------------------------------------------------------------
__global__ __launch_bounds__(256) void attn_kernel(
    const float* __restrict__ Q, const float* __restrict__ K,
    const float* __restrict__ V, float* __restrict__ O)
{
    extern __shared__ float sm[];
    float* Ks = sm;
    float* Vs = sm + SS * HD;

    const int blk = blockIdx.x;
    const int n   = blk >> 4;
    const int h   = blk & 15;
    const int hk  = h >> 2;
    const int tid = threadIdx.x;

    for (int i = 0; i < 16; i++) {
        int flat = tid + i * 256;
        int j  = flat >> 4;
        int e4 = flat & 15;
        size_t goff = ((size_t)(n * SS + j) * (HKV * HD) + hk * HD) / 4 + e4;
        ((float4*)Ks)[flat] = ((const float4*)K)[goff];
        ((float4*)Vs)[flat] = ((const float4*)V)[goff];
    }
    __syncthreads();

    float4 q[16];
    const float4* qp = (const float4*)(Q + (size_t)(n * SS + tid) * DD + h * HD);
    #pragma unroll
    for (int i = 0; i < 16; i++) q[i] = qp[i];

    float4 o[16];
    #pragma unroll
    for (int i = 0; i < 16; i++) o[i] = make_float4(0.f, 0.f, 0.f, 0.f);
    float l = 0.f;

    const int jmax = (tid < N_IMG) ? N_IMG : SS;
    const float sc = 0.125f / 50.0f;

    for (int j = 0; j < jmax; j++) {
        const float4* kr = (const float4*)(Ks + j * HD);
        float d0 = 0.f, d1 = 0.f, d2 = 0.f, d3 = 0.f;
        #pragma unroll
        for (int i = 0; i < 16; i++) {
            float4 kv = kr[i];
            d0 = fmaf(q[i].x, kv.x, d0);
            d1 = fmaf(q[i].y, kv.y, d1);
            d2 = fmaf(q[i].z, kv.z, d2);
            d3 = fmaf(q[i].w, kv.w, d3);
        }
        float d = (d0 + d1) + (d2 + d3);
        float sVal = 50.0f * tanhf(d * sc);
        float p = __expf(sVal);
        l += p;
        const float4* vr = (const float4*)(Vs + j * HD);
        #pragma unroll
        for (int i = 0; i < 16; i++) {
            float4 vv = vr[i];
            o[i].x = fmaf(p, vv.x, o[i].x);
            o[i].y = fmaf(p, vv.y, o[i].y);
            o[i].z = fmaf(p, vv.z, o[i].z);
            o[i].w = fmaf(p, vv.w, o[i].w);
        }
    }

    float inv = 1.0f / l;
    float4* op = (float4*)(O + (size_t)(n * SS + tid) * DD + h * HD);
    #pragma unroll
    for (int i = 0; i < 16; i++) {
        float4 t = o[i];
        op[i] = make_float4(t.x * inv, t.y * inv, t.z * inv, t.w * inv);
    }
}

// ---------------------------------------------------------------------------
extern "C" void kernel_launch(void* const* d_in, const int* in_sizes, int n_in,
                              void* d_out, int out_size)
{
    const float* x        = (const float*)d_in[0];
    // d_in[1] = attn_mask (structural; not read)
    const float* rope_cos = (const float*)d_in[2];
    const float* rope_sin = (const float*)d_in[3];
    const float* Wq       = (const float*)d_in[4];
    const float* Wk       = (const float*)d_in[5];
    const float* Wv       = (const float*)d_in[6];
    const float* Wo       = (const float*)d_in[7];
    const float* q_scale  = (const float*)d_in[8];
    const float* k_scale  = (const float*)d_in[9];
    float* out = (float*)d_out;

    float *pQ, *pK, *pV, *pAO;
    cudaGetSymbolAddress((void**)&pQ,  g_Q);
    cudaGetSymbolAddress((void**)&pK,  g_K);
    cudaGetSymbolAddress((void**)&pV,  g_V);
    cudaGetSymbolAddress((void**)&pAO, g_AO);

    cudaFuncSetAttribute(gemm_mma_tf32,
                         cudaFuncAttributeMaxDynamicSharedMemorySize, GEMM_SMEM);

    // 1) Projections (tf32 mma.sync GEMM)
    gemm_mma_tf32<<<dim3(DD / 128, NROWS / 128), 256, GEMM_SMEM>>>(x, Wq, pQ, DD, DD);
    gemm_mma_tf32<<<dim3((HKV * HD) / 128, NROWS / 128), 256, GEMM_SMEM>>>(x, Wk, pK, HKV * HD, DD);
    gemm_mma_tf32<<<dim3((HKV * HD) / 128, NROWS / 128), 256, GEMM_SMEM>>>(x, Wv, pV, HKV * HD, DD);

    // 2) RMSNorm + RoPE (in place)
    normrope_kernel<<<(NROWS * HH + NROWS * HKV) / 8, 256>>>(rope_cos, rope_sin,
                                                             q_scale, k_scale);

    // 3) Attention
    static const int ATTN_SMEM = 2 * SS * HD * (int)sizeof(float);  // 128 KB
    cudaFuncSetAttribute(attn_kernel, cudaFuncAttributeMaxDynamicSharedMemorySize,
                         ATTN_SMEM);
    attn_kernel<<<NSEQ * HH, 256, ATTN_SMEM>>>(pQ, pK, pV, pAO);

    // 4) Output projection (tf32 mma.sync GEMM)
    gemm_mma_tf32<<<dim3(DD / 128, NROWS / 128), 256, GEMM_SMEM>>>(pAO, Wo, out, DD, DD);
}

// round 8
// speedup vs baseline: 1.2768x; 1.2768x over previous
#include <cuda_runtime.h>
#include <cuda_fp16.h>
#include <cstdint>
#include <math.h>

#define BB 4
#define TT 16
#define SS 256
#define DD 1024
#define HH 16
#define HKV 4
#define HD 64
#define NSEQ (BB*TT)
#define NROWS (NSEQ*SS)
#define N_IMG 240

__device__ float g_Q[NROWS * DD];
__device__ float g_K[NROWS * HKV * HD];
__device__ float g_V[NROWS * HKV * HD];
__device__ float g_AO[NROWS * DD];

// ---------------------------------------------------------------------------
__device__ __forceinline__ float to_tf32(float x) {
    float y; asm("cvt.rna.tf32.f32 %0, %1;" : "=f"(y) : "f"(x)); return y;
}
__device__ __forceinline__ void mma_tf32(float* d, const uint32_t* a, const uint32_t* b) {
    asm volatile(
        "mma.sync.aligned.m16n8k8.row.col.f32.tf32.tf32.f32 "
        "{%0,%1,%2,%3}, {%4,%5,%6,%7}, {%8,%9}, {%0,%1,%2,%3};"
        : "+f"(d[0]), "+f"(d[1]), "+f"(d[2]), "+f"(d[3])
        : "r"(a[0]), "r"(a[1]), "r"(a[2]), "r"(a[3]), "r"(b[0]), "r"(b[1]));
}
__device__ __forceinline__ void mma_f16(float* d, const uint32_t* a, uint32_t b0, uint32_t b1) {
    asm volatile(
        "mma.sync.aligned.m16n8k16.row.col.f32.f16.f16.f32 "
        "{%0,%1,%2,%3}, {%4,%5,%6,%7}, {%8,%9}, {%0,%1,%2,%3};"
        : "+f"(d[0]), "+f"(d[1]), "+f"(d[2]), "+f"(d[3])
        : "r"(a[0]), "r"(a[1]), "r"(a[2]), "r"(a[3]), "r"(b0), "r"(b1));
}
__device__ __forceinline__ uint32_t pack_h2(float a, float b) {
    __half2 h = __floats2half2_rn(a, b);
    return *reinterpret_cast<uint32_t*>(&h);
}

// ---------------------------------------------------------------------------
// TF32 GEMM body (same as proven R5 kernel, factored for fusion)
// ---------------------------------------------------------------------------
#define A_STRIDE 36
#define B_STRIDE 136
#define A_SZ (128 * A_STRIDE)
#define B_SZ (32 * B_STRIDE)
#define GEMM_SMEM ((2 * (A_SZ + B_SZ)) * (int)sizeof(float))

__device__ __forceinline__ void gemm_body(
    const float* __restrict__ A, const float* __restrict__ W,
    float* __restrict__ C, int N, int K, int m0, int n0, float* sm)
{
    float* As[2] = { sm, sm + A_SZ };
    float* Bs[2] = { sm + 2 * A_SZ, sm + 2 * A_SZ + B_SZ };

    const int tid  = threadIdx.x;
    const int wid  = tid >> 5;
    const int lane = tid & 31;
    const int grp  = lane >> 2;
    const int tig  = lane & 3;
    const int m_off = (wid & 1) * 64;
    const int n_off = (wid >> 1) * 32;

    float acc[4][4][4];
    #pragma unroll
    for (int mt = 0; mt < 4; mt++)
        #pragma unroll
        for (int nt = 0; nt < 4; nt++)
            #pragma unroll
            for (int i = 0; i < 4; i++) acc[mt][nt][i] = 0.f;

    float4 ldA[4], ldB[4];
    #pragma unroll
    for (int s = 0; s < 4; s++) {
        int idx = tid + s * 256;
        int am = idx >> 3, ak4 = idx & 7;
        ldA[s] = *(const float4*)(A + (size_t)(m0 + am) * K + ak4 * 4);
        int bk = idx >> 5, bn4 = idx & 31;
        ldB[s] = *(const float4*)(W + (size_t)bk * N + n0 + bn4 * 4);
    }

    const int KT = K >> 5;
    for (int kt = 0; kt < KT; kt++) {
        float* Ab = As[kt & 1];
        float* Bb = Bs[kt & 1];
        #pragma unroll
        for (int s = 0; s < 4; s++) {
            int idx = tid + s * 256;
            int am = idx >> 3, ak4 = idx & 7;
            float4 v = ldA[s];
            *(float4*)(Ab + am * A_STRIDE + ak4 * 4) = make_float4(
                to_tf32(v.x), to_tf32(v.y), to_tf32(v.z), to_tf32(v.w));
            int bk = idx >> 5, bn4 = idx & 31;
            float4 w = ldB[s];
            *(float4*)(Bb + bk * B_STRIDE + bn4 * 4) = make_float4(
                to_tf32(w.x), to_tf32(w.y), to_tf32(w.z), to_tf32(w.w));
        }
        __syncthreads();
        if (kt + 1 < KT) {
            const int kn = (kt + 1) * 32;
            #pragma unroll
            for (int s = 0; s < 4; s++) {
                int idx = tid + s * 256;
                int am = idx >> 3, ak4 = idx & 7;
                ldA[s] = *(const float4*)(A + (size_t)(m0 + am) * K + kn + ak4 * 4);
                int bk = idx >> 5, bn4 = idx & 31;
                ldB[s] = *(const float4*)(W + (size_t)(kn + bk) * N + n0 + bn4 * 4);
            }
        }
        #pragma unroll
        for (int ks = 0; ks < 4; ks++) {
            const int k = ks * 8;
            uint32_t af[4][4], bf[4][2];
            #pragma unroll
            for (int mt = 0; mt < 4; mt++) {
                const int row = m_off + mt * 16 + grp;
                af[mt][0] = __float_as_uint(Ab[row * A_STRIDE + k + tig]);
                af[mt][1] = __float_as_uint(Ab[(row + 8) * A_STRIDE + k + tig]);
                af[mt][2] = __float_as_uint(Ab[row * A_STRIDE + k + tig + 4]);
                af[mt][3] = __float_as_uint(Ab[(row + 8) * A_STRIDE + k + tig + 4]);
            }
            #pragma unroll
            for (int nt = 0; nt < 4; nt++) {
                const int col = n_off + nt * 8 + grp;
                bf[nt][0] = __float_as_uint(Bb[(k + tig) * B_STRIDE + col]);
                bf[nt][1] = __float_as_uint(Bb[(k + tig + 4) * B_STRIDE + col]);
            }
            #pragma unroll
            for (int mt = 0; mt < 4; mt++)
                #pragma unroll
                for (int nt = 0; nt < 4; nt++)
                    mma_tf32(acc[mt][nt], af[mt], bf[nt]);
        }
    }

    #pragma unroll
    for (int mt = 0; mt < 4; mt++) {
        const int row = m0 + m_off + mt * 16 + grp;
        #pragma unroll
        for (int nt = 0; nt < 4; nt++) {
            const int col = n0 + n_off + nt * 8 + 2 * tig;
            *(float2*)(C + (size_t)row * N + col) =
                make_float2(acc[mt][nt][0], acc[mt][nt][1]);
            *(float2*)(C + (size_t)(row + 8) * N + col) =
                make_float2(acc[mt][nt][2], acc[mt][nt][3]);
        }
    }
}

// Fused QKV: blockIdx.x 0-7 -> Q cols, 8-9 -> K, 10-11 -> V
__global__ __launch_bounds__(256) void gemm_qkv(
    const float* __restrict__ A, const float* __restrict__ Wq,
    const float* __restrict__ Wk, const float* __restrict__ Wv)
{
    extern __shared__ float sm[];
    const int ct = blockIdx.x;
    const float* W; float* C; int N, n0;
    if (ct < 8)       { W = Wq; C = g_Q; N = DD;       n0 = ct * 128; }
    else if (ct < 10) { W = Wk; C = g_K; N = HKV * HD; n0 = (ct - 8) * 128; }
    else              { W = Wv; C = g_V; N = HKV * HD; n0 = (ct - 10) * 128; }
    gemm_body(A, W, C, N, DD, blockIdx.y * 128, n0, sm);
}

__global__ __launch_bounds__(256) void gemm_mma_tf32(
    const float* __restrict__ A, const float* __restrict__ W,
    float* __restrict__ C, int N, int K)
{
    extern __shared__ float sm[];
    gemm_body(A, W, C, N, K, blockIdx.y * 128, blockIdx.x * 128, sm);
}

// ---------------------------------------------------------------------------
// RMSNorm + RoPE (unchanged)
// ---------------------------------------------------------------------------
__global__ __launch_bounds__(256) void normrope_kernel(
    const float* __restrict__ rope_cos, const float* __restrict__ rope_sin,
    const float* __restrict__ q_scale, const float* __restrict__ k_scale)
{
    const int w    = blockIdx.x * 8 + (threadIdx.x >> 5);
    const int lane = threadIdx.x & 31;

    float* ptr; const float* sc; int s;
    const int NQ = NROWS * HH;
    if (w < NQ) {
        int ns = w >> 4, h = w & 15;
        ptr = g_Q + (size_t)ns * DD + h * HD;
        s = ns & (SS - 1); sc = q_scale;
    } else {
        int r = w - NQ, ns = r >> 2, hk = r & 3;
        ptr = g_K + (size_t)ns * (HKV * HD) + hk * HD;
        s = ns & (SS - 1); sc = k_scale;
    }

    float a = ptr[lane];
    float b = ptr[lane + 32];
    float ssq = a * a + b * b;
    #pragma unroll
    for (int off = 16; off > 0; off >>= 1)
        ssq += __shfl_xor_sync(0xFFFFFFFFu, ssq, off);
    float r = rsqrtf(ssq * (1.0f / 64.0f) + 1e-6f);

    float an = a * r * sc[lane];
    float bn = b * r * sc[lane + 32];
    float c  = rope_cos[s * 32 + lane];
    float sn = rope_sin[s * 32 + lane];
    ptr[lane]      = an * c - bn * sn;
    ptr[lane + 32] = bn * c + an * sn;
}

// ---------------------------------------------------------------------------
// Flash attention, f16 mma. CTA = (n, hk, q-quarter); 4 q-heads share K/V.
// Warp: head = hk*4 + (w>>1), 32 q-rows at (w&1)*32. Online softmax.
// ---------------------------------------------------------------------------
#define QP_STR 36
#define VT_STR 132
#define ATTN_SMEM ((512 * QP_STR + 64 * VT_STR) * 4)   // 107520 B

__global__ __launch_bounds__(256) void attn_mma(
    const float* __restrict__ Q, const float* __restrict__ Kg,
    const float* __restrict__ Vg, float* __restrict__ O)
{
    extern __shared__ uint32_t smu[];
    uint32_t* Qp = smu;                  // [256][36] 4 heads x 64 rows, h2 pairs
    uint32_t* Kp = smu + 256 * QP_STR;   // [256][36]
    uint32_t* Vt = smu + 512 * QP_STR;   // [64][132] hd-major, kv pairs

    const int blk = blockIdx.x;
    const int n = blk >> 4, hk = (blk >> 2) & 3, qq = blk & 3;
    const int tid = threadIdx.x, w = tid >> 5, lane = tid & 31;
    const int grp = lane >> 2, tig = lane & 3;

    #pragma unroll
    for (int i = 0; i < 16; i++) {
        int flat = tid + i * 256;
        int hrow = flat >> 4, c4 = flat & 15;
        int head = hrow >> 6, row = hrow & 63;
        float4 v = *(const float4*)(
            Q + (size_t)(n * SS + qq * 64 + row) * DD + (hk * 4 + head) * HD + c4 * 4);
        Qp[hrow * QP_STR + c4 * 2]     = pack_h2(v.x, v.y);
        Qp[hrow * QP_STR + c4 * 2 + 1] = pack_h2(v.z, v.w);
    }
    #pragma unroll
    for (int i = 0; i < 16; i++) {
        int flat = tid + i * 256;
        int row = flat >> 4, c4 = flat & 15;
        float4 v = *(const float4*)(
            Kg + (size_t)(n * SS + row) * (HKV * HD) + hk * HD + c4 * 4);
        Kp[row * QP_STR + c4 * 2]     = pack_h2(v.x, v.y);
        Kp[row * QP_STR + c4 * 2 + 1] = pack_h2(v.z, v.w);
    }
    #pragma unroll
    for (int i = 0; i < 32; i++) {
        int flat = tid + i * 256;            // 64 hd x 128 kv-pairs
        int hd = flat & 63, kp = flat >> 6;
        const float* vp = Vg + (size_t)(n * SS + 2 * kp) * (HKV * HD) + hk * HD + hd;
        Vt[hd * VT_STR + kp] = pack_h2(vp[0], vp[HKV * HD]);
    }
    __syncthreads();

    const int qbase = (w >> 1) * 64 + (w & 1) * 32;   // row in Qp
    const int qrow0 = qq * 64 + (w & 1) * 32;         // global seq row

    float o[2][8][4];
    #pragma unroll
    for (int mt = 0; mt < 2; mt++)
        #pragma unroll
        for (int nt = 0; nt < 8; nt++)
            #pragma unroll
            for (int e = 0; e < 4; e++) o[mt][nt][e] = 0.f;
    float m_run[2][2] = {{-1e30f,-1e30f},{-1e30f,-1e30f}};
    float l_run[2][2] = {{0.f,0.f},{0.f,0.f}};

    for (int c = 0; c < 4; c++) {
        float s[2][8][4];
        #pragma unroll
        for (int mt = 0; mt < 2; mt++)
            #pragma unroll
            for (int nt = 0; nt < 8; nt++)
                #pragma unroll
                for (int e = 0; e < 4; e++) s[mt][nt][e] = 0.f;

        // S = Q @ Kc^T (k-dim = hd 64, 4 ksteps of 16)
        #pragma unroll
        for (int ks = 0; ks < 4; ks++) {
            uint32_t a[2][4];
            #pragma unroll
            for (int mt = 0; mt < 2; mt++) {
                int r = qbase + mt * 16 + grp;
                a[mt][0] = Qp[r * QP_STR + 8 * ks + tig];
                a[mt][1] = Qp[(r + 8) * QP_STR + 8 * ks + tig];
                a[mt][2] = Qp[r * QP_STR + 8 * ks + tig + 4];
                a[mt][3] = Qp[(r + 8) * QP_STR + 8 * ks + tig + 4];
            }
            #pragma unroll
            for (int nt = 0; nt < 8; nt++) {
                int kr = c * 64 + nt * 8 + grp;
                uint32_t b0 = Kp[kr * QP_STR + 8 * ks + tig];
                uint32_t b1 = Kp[kr * QP_STR + 8 * ks + tig + 4];
                #pragma unroll
                for (int mt = 0; mt < 2; mt++) mma_f16(s[mt][nt], a[mt], b0, b1);
            }
        }

        // tanh cap + mask + online softmax; rows grp(+8) => half 0/1
        #pragma unroll
        for (int mt = 0; mt < 2; mt++) {
            #pragma unroll
            for (int half = 0; half < 2; half++) {
                int qrow = qrow0 + mt * 16 + grp + half * 8;
                float sv[8][2];
                float mx = -1e30f;
                #pragma unroll
                for (int nt = 0; nt < 8; nt++) {
                    #pragma unroll
                    for (int e2 = 0; e2 < 2; e2++) {
                        int kcol = c * 64 + nt * 8 + 2 * tig + e2;
                        float d = s[mt][nt][half * 2 + e2] * 0.125f;
                        float ex = __expf(d * 0.04f);       // e^{2d/50}
                        float t = 50.f - 100.f / (ex + 1.f); // 50*tanh(d/50)
                        bool masked = (qrow < N_IMG) && (kcol >= N_IMG);
                        sv[nt][e2] = masked ? -1e30f : t;
                        mx = fmaxf(mx, sv[nt][e2]);
                    }
                }
                mx = fmaxf(mx, __shfl_xor_sync(0xFFFFFFFFu, mx, 1));
                mx = fmaxf(mx, __shfl_xor_sync(0xFFFFFFFFu, mx, 2));
                float m_new = fmaxf(m_run[mt][half], mx);
                float corr = __expf(m_run[mt][half] - m_new);
                m_run[mt][half] = m_new;
                float lsum = 0.f;
                #pragma unroll
                for (int nt = 0; nt < 8; nt++) {
                    #pragma unroll
                    for (int e2 = 0; e2 < 2; e2++) {
                        float p = __expf(sv[nt][e2] - m_new);
                        s[mt][nt][half * 2 + e2] = p;
                        lsum += p;
                    }
                }
                lsum += __shfl_xor_sync(0xFFFFFFFFu, lsum, 1);
                lsum += __shfl_xor_sync(0xFFFFFFFFu, lsum, 2);
                l_run[mt][half] = l_run[mt][half] * corr + lsum;
                #pragma unroll
                for (int nt = 0; nt < 8; nt++) {
                    o[mt][nt][half * 2]     *= corr;
                    o[mt][nt][half * 2 + 1] *= corr;
                }
            }
        }

        // O += P @ Vc (k-dim = kv 64; P frags repacked from S accum layout)
        #pragma unroll
        for (int ks = 0; ks < 4; ks++) {
            uint32_t a[2][4];
            #pragma unroll
            for (int mt = 0; mt < 2; mt++) {
                a[mt][0] = pack_h2(s[mt][2 * ks][0],     s[mt][2 * ks][1]);
                a[mt][1] = pack_h2(s[mt][2 * ks][2],     s[mt][2 * ks][3]);
                a[mt][2] = pack_h2(s[mt][2 * ks + 1][0], s[mt][2 * ks + 1][1]);
                a[mt][3] = pack_h2(s[mt][2 * ks + 1][2], s[mt][2 * ks + 1][3]);
            }
            #pragma unroll
            for (int nt = 0; nt < 8; nt++) {
                int hd = nt * 8 + grp;
                uint32_t b0 = Vt[hd * VT_STR + c * 32 + 8 * ks + tig];
                uint32_t b1 = Vt[hd * VT_STR + c * 32 + 8 * ks + tig + 4];
                #pragma unroll
                for (int mt = 0; mt < 2; mt++) mma_f16(o[mt][nt], a[mt], b0, b1);
            }
        }
    }

    const int head = hk * 4 + (w >> 1);
    #pragma unroll
    for (int mt = 0; mt < 2; mt++) {
        int r0 = qrow0 + mt * 16 + grp;
        #pragma unroll
        for (int half = 0; half < 2; half++) {
            float inv = 1.f / l_run[mt][half];
            float* op = O + (size_t)(n * SS + r0 + half * 8) * DD + head * HD;
            #pragma unroll
            for (int nt = 0; nt < 8; nt++)
                *(float2*)(op + nt * 8 + 2 * tig) = make_float2(
                    o[mt][nt][half * 2] * inv, o[mt][nt][half * 2 + 1] * inv);
        }
    }
}

// ---------------------------------------------------------------------------
extern "C" void kernel_launch(void* const* d_in, const int* in_sizes, int n_in,
                              void* d_out, int out_size)
{
    const float* x        = (const float*)d_in[0];
    const float* rope_cos = (const float*)d_in[2];
    const float* rope_sin = (const float*)d_in[3];
    const float* Wq       = (const float*)d_in[4];
    const float* Wk       = (const float*)d_in[5];
    const float* Wv       = (const float*)d_in[6];
    const float* Wo       = (const float*)d_in[7];
    const float* q_scale  = (const float*)d_in[8];
    const float* k_scale  = (const float*)d_in[9];
    float* out = (float*)d_out;

    float *pQ, *pK, *pV, *pAO;
    cudaGetSymbolAddress((void**)&pQ,  g_Q);
    cudaGetSymbolAddress((void**)&pK,  g_K);
    cudaGetSymbolAddress((void**)&pV,  g_V);
    cudaGetSymbolAddress((void**)&pAO, g_AO);

    cudaFuncSetAttribute(gemm_qkv, cudaFuncAttributeMaxDynamicSharedMemorySize, GEMM_SMEM);
    cudaFuncSetAttribute(gemm_mma_tf32, cudaFuncAttributeMaxDynamicSharedMemorySize, GEMM_SMEM);
    cudaFuncSetAttribute(attn_mma, cudaFuncAttributeMaxDynamicSharedMemorySize, ATTN_SMEM);

    // 1) Fused Q/K/V projections
    gemm_qkv<<<dim3(12, NROWS / 128), 256, GEMM_SMEM>>>(x, Wq, Wk, Wv);

    // 2) RMSNorm + RoPE
    normrope_kernel<<<(NROWS * HH + NROWS * HKV) / 8, 256>>>(rope_cos, rope_sin,
                                                             q_scale, k_scale);

    // 3) Flash attention (f16 mma)
    attn_mma<<<NSEQ * HKV * 4, 256, ATTN_SMEM>>>(pQ, pK, pV, pAO);

    // 4) Output projection
    gemm_mma_tf32<<<dim3(DD / 128, NROWS / 128), 256, GEMM_SMEM>>>(pAO, Wo, out, DD, DD);
}